// round 4
// baseline (speedup 1.0000x reference)
#include <cuda_runtime.h>
#include <cstdint>
#include <math.h>

// Problem constants
#define B_   64
#define S_   1024
#define I_   256
#define H_   512
#define O_   512
#define G3H  (3 * H_)

// Recurrence kernel config
#define GR   128   // grid CTAs (<= 148 SMs -> all resident, own barrier is safe)
#define RT   256   // threads per CTA

// ---------------------------------------------------------------------------
// Scratch (device globals; no runtime allocation allowed)
// ---------------------------------------------------------------------------
__device__ float    g_gi   [(size_t)S_ * G3H * B_];   // gi staging [t][n][b]  (reused by both layers)
__device__ float    g_hseq0[(size_t)S_ * B_ * H_];    // layer-0 outputs [t][b][h]
__device__ float    g_hseq1[(size_t)S_ * B_ * H_];    // layer-1 outputs [t][b][h]
__device__ float    g_hT   [2 * H_ * B_];             // double-buffered transposed h [buf][j][b]
__device__ unsigned g_bar;                             // grid barrier counter

// ---------------------------------------------------------------------------
// SGEMM with bias:  C[M,N] = A[M,K] @ Bw[N,K]^T + bias[N]
// BM=128, BN=64, BK=16, 256 threads, 8x4 register tile per thread.
// MODE selects the epilogue scatter:
//   0: A rows are m = b*S + s  (x layout)   -> out[t][n][b]   (gi layout)
//   1: A rows are m = t*B + b  (hseq layout)-> out[t][n][b]   (gi layout)
//   2: A rows are m = t*B + b               -> out[b][t][n]   (logits layout)
// All dims are multiples of the tile sizes for this problem -> no edge guards.
// ---------------------------------------------------------------------------
template <int MODE>
__global__ void __launch_bounds__(256)
sgemm_bias(const float* __restrict__ A, const float* __restrict__ Bw,
           const float* __restrict__ bias, float* __restrict__ out,
           int M, int N, int K)
{
    __shared__ float As[16][132];   // padded: stride 132 floats = 528 B (16B multiple)
    __shared__ float Bs[16][68];    // padded: stride 68 floats  = 272 B (16B multiple)

    const int tid = threadIdx.x;
    const int m0  = blockIdx.y * 128;
    const int n0  = blockIdx.x * 64;
    const int tx  = tid & 15;       // 4 cols of N each
    const int ty  = tid >> 4;       // 8 rows of M each

    const float* Ab = A  + (size_t)m0 * K;
    const float* Bb = Bw + (size_t)n0 * K;

    float acc[8][4];
#pragma unroll
    for (int i = 0; i < 8; i++)
#pragma unroll
        for (int j = 0; j < 4; j++) acc[i][j] = 0.f;

    const int lr = tid >> 2;         // loader row (0..63)
    const int lk = (tid & 3) * 4;    // loader k offset (0,4,8,12)

    for (int kt = 0; kt < K; kt += 16) {
#pragma unroll
        for (int p = 0; p < 2; p++) {
            float4 v = *(const float4*)&Ab[(size_t)(lr + p * 64) * K + kt + lk];
            As[lk + 0][lr + p * 64] = v.x;
            As[lk + 1][lr + p * 64] = v.y;
            As[lk + 2][lr + p * 64] = v.z;
            As[lk + 3][lr + p * 64] = v.w;
        }
        {
            float4 v = *(const float4*)&Bb[(size_t)lr * K + kt + lk];
            Bs[lk + 0][lr] = v.x;
            Bs[lk + 1][lr] = v.y;
            Bs[lk + 2][lr] = v.z;
            Bs[lk + 3][lr] = v.w;
        }
        __syncthreads();

#pragma unroll
        for (int k = 0; k < 16; k++) {
            float a[8], bb[4];
            *(float4*)&bb[0] = *(const float4*)&Bs[k][tx * 4];
            *(float4*)&a[0]  = *(const float4*)&As[k][ty * 8];
            *(float4*)&a[4]  = *(const float4*)&As[k][ty * 8 + 4];
#pragma unroll
            for (int i = 0; i < 8; i++)
#pragma unroll
                for (int j = 0; j < 4; j++)
                    acc[i][j] += a[i] * bb[j];
        }
        __syncthreads();
    }

    float bv[4];
    *(float4*)bv = *(const float4*)&bias[n0 + tx * 4];

#pragma unroll
    for (int i = 0; i < 8; i++) {
        int m = m0 + ty * 8 + i;
        if (MODE == 2) {
            int t = m >> 6, b = m & 63;
            float4 c;
            c.x = acc[i][0] + bv[0];
            c.y = acc[i][1] + bv[1];
            c.z = acc[i][2] + bv[2];
            c.w = acc[i][3] + bv[3];
            *(float4*)&out[((size_t)b * S_ + t) * O_ + n0 + tx * 4] = c;
        } else {
            int t, b;
            if (MODE == 0) { t = m & (S_ - 1); b = m >> 10; }
            else           { t = m >> 6;       b = m & 63;  }
#pragma unroll
            for (int j = 0; j < 4; j++) {
                int n = n0 + tx * 4 + j;
                out[((size_t)t * G3H + n) * B_ + b] = acc[i][j] + bv[j];
            }
        }
    }
}

// ---------------------------------------------------------------------------
// Persistent GRU recurrence for one layer.
// 128 CTAs; CTA c owns H-columns [4c, 4c+4). Per step:
//   gh[b, g*H + j] = sum_k h[b,k] * W_hh[g*H+j, k]  (W slice resident in smem)
// then gates + h update; h exchanged via global hT (transposed [j][b]),
// synchronized by an atomic-counter grid barrier (all 128 CTAs are wave-1
// resident: 1 CTA/SM due to 191.5 KB smem, grid < SM count).
// smem layout (floats):
//   hs  [512][64]       @ 0       (128 KB)  full transposed h state
//   Ws  [512][4][4]     @ 32768   ( 32 KB)  W slice, k-major, [k][jc][gate]
//   P   [8][4][64][3]   @ 40960   ( 24 KB)  k-split partial sums
//   gis [3][4][64]      @ 47104   (  3 KB)  staged gi for this step
//   bh  [12]            @ 47872              b_hh slice
// ---------------------------------------------------------------------------
#define REC_SMEM_FLOATS 47884
#define REC_SMEM_BYTES  (REC_SMEM_FLOATS * 4)

__device__ __forceinline__ float sigmoidf_(float x) {
    return 1.f / (1.f + expf(-x));
}

__global__ void __launch_bounds__(RT, 1)
gru_rec(const float* __restrict__ gi,    // [S][3H][B]
        const float* __restrict__ Whh,   // [3H][H]
        const float* __restrict__ bhh,   // [3H]
        float* __restrict__ hT,          // [2][H][B]
        float* __restrict__ hseq,        // [S][B][H]
        float* __restrict__ hfin,        // [B][H]  (final h -> d_out tail)
        unsigned* __restrict__ bar)
{
    extern __shared__ float sm[];
    float* hs  = sm;              // 32768
    float* Ws  = sm + 32768;      // 8192
    float* P   = sm + 40960;      // 6144
    float* gis = sm + 47104;      // 768
    float* bh  = sm + 47872;      // 12

    const int tid   = threadIdx.x;
    const int jbase = blockIdx.x * 4;

    // Preload W_hh slice (12 rows x 512) into smem, k-major, gates packed in float4.
    for (int i = tid; i < 12 * 512; i += RT) {
        int k = i & 511;
        int r = i >> 9;                 // 0..11
        int g = r % 3, jc = r / 3;
        Ws[(k * 4 + jc) * 4 + g] = Whh[((size_t)(g * H_ + jbase + jc)) * H_ + k];
    }
    if (tid < 12) {
        int g = tid % 3, jc = tid / 3;
        bh[jc * 3 + g] = bhh[g * H_ + jbase + jc];
    }

    // Compute-phase thread mapping: 8 k-splits x 4 jc x 8 b-groups(8 b each)
    const int ks   = tid >> 5;
    const int lane = tid & 31;
    const int jc   = lane >> 3;
    const int b0   = (lane & 7) * 8;
    const int k0   = ks * 64;

    const float4* Ws4  = (const float4*)Ws;
    const float4* hs4c = (const float4*)hs;

    // Finalize-phase mapping: one (b, jc) per thread
    const int fb  = tid & 63;
    const int fjc = tid >> 6;
    const int fj  = jbase + fjc;

    for (int t = 0; t < S_; t++) {
        const int cur = t & 1;

        // Stage full h state (transposed) into smem: 8192 float4
        {
            const float4* hsrc = (const float4*)(hT + cur * H_ * B_);
            float4* hdst = (float4*)hs;
            for (int i = tid; i < 8192; i += RT) hdst[i] = hsrc[i];
        }
        // Stage this step's gi slice (12 rows x 64 b)
        for (int i = tid; i < 768; i += RT) {
            int b = i & 63;
            int r = i >> 6;
            int g = r % 3, jcc = r / 3;
            gis[(g * 4 + jcc) * 64 + b] =
                gi[((size_t)t * G3H + g * H_ + jbase + jcc) * B_ + b];
        }
        __syncthreads();

        // Partial dot products over this thread's k range
        float a0[8], a1[8], a2[8];
#pragma unroll
        for (int i = 0; i < 8; i++) { a0[i] = 0.f; a1[i] = 0.f; a2[i] = 0.f; }

#pragma unroll 4
        for (int k = k0; k < k0 + 64; k++) {
            float4 w  = Ws4[k * 4 + jc];
            float4 h0 = hs4c[k * 16 + (b0 >> 2)];
            float4 h1 = hs4c[k * 16 + (b0 >> 2) + 1];
            float hv[8];
            *(float4*)&hv[0] = h0;
            *(float4*)&hv[4] = h1;
#pragma unroll
            for (int i = 0; i < 8; i++) {
                a0[i] += hv[i] * w.x;
                a1[i] += hv[i] * w.y;
                a2[i] += hv[i] * w.z;
            }
        }

        // Store partials (24 consecutive floats -> 6 x float4)
        {
            float val[24];
#pragma unroll
            for (int i = 0; i < 8; i++) {
                val[i * 3 + 0] = a0[i];
                val[i * 3 + 1] = a1[i];
                val[i * 3 + 2] = a2[i];
            }
            float* pb = P + ((ks * 4 + jc) * 64 + b0) * 3;
#pragma unroll
            for (int q = 0; q < 6; q++) ((float4*)pb)[q] = ((const float4*)val)[q];
        }
        __syncthreads();

        // Reduce k-splits + gate math + h update (one (b,jc) per thread)
        {
            float gh0 = 0.f, gh1 = 0.f, gh2 = 0.f;
#pragma unroll
            for (int s = 0; s < 8; s++) {
                const float* pp = P + ((s * 4 + fjc) * 64 + fb) * 3;
                gh0 += pp[0];
                gh1 += pp[1];
                gh2 += pp[2];
            }
            gh0 += bh[fjc * 3 + 0];
            gh1 += bh[fjc * 3 + 1];
            gh2 += bh[fjc * 3 + 2];

            float gir = gis[(0 * 4 + fjc) * 64 + fb];
            float giz = gis[(1 * 4 + fjc) * 64 + fb];
            float gin = gis[(2 * 4 + fjc) * 64 + fb];

            float r_ = sigmoidf_(gir + gh0);
            float z_ = sigmoidf_(giz + gh1);
            float n_ = tanhf(gin + r_ * gh2);
            float hold = hs[fj * 64 + fb];
            float hn = (1.f - z_) * n_ + z_ * hold;

            hT[(cur ^ 1) * H_ * B_ + fj * 64 + fb] = hn;
            hseq[(size_t)t * B_ * H_ + (size_t)fb * H_ + fj] = hn;
            if (t == S_ - 1) hfin[fb * H_ + fj] = hn;
        }
        __syncthreads();

        // Grid barrier (sense-free: monotonically increasing counter)
        if (tid == 0) {
            __threadfence();
            atomicAdd(bar, 1u);
            unsigned tgt = (unsigned)(t + 1) * GR;
            while (*((volatile unsigned*)bar) < tgt) __nanosleep(64);
            __threadfence();
        }
        __syncthreads();
    }
}

// ---------------------------------------------------------------------------
// Launch
// ---------------------------------------------------------------------------
extern "C" void kernel_launch(void* const* d_in, const int* in_sizes, int n_in,
                              void* d_out, int out_size)
{
    const float* x    = (const float*)d_in[0];
    const float* Wih0 = (const float*)d_in[1];
    const float* Whh0 = (const float*)d_in[2];
    const float* bih0 = (const float*)d_in[3];
    const float* bhh0 = (const float*)d_in[4];
    const float* Wih1 = (const float*)d_in[5];
    const float* Whh1 = (const float*)d_in[6];
    const float* bih1 = (const float*)d_in[7];
    const float* bhh1 = (const float*)d_in[8];
    const float* Wfc  = (const float*)d_in[9];
    const float* bfc  = (const float*)d_in[10];

    float* out = (float*)d_out;                       // logits [B][S][O]
    float* hid = out + (size_t)B_ * S_ * O_;          // hidden [2][B][H]

    float *gi, *h0, *h1, *hT;
    unsigned* bar;
    cudaGetSymbolAddress((void**)&gi,  g_gi);
    cudaGetSymbolAddress((void**)&h0,  g_hseq0);
    cudaGetSymbolAddress((void**)&h1,  g_hseq1);
    cudaGetSymbolAddress((void**)&hT,  g_hT);
    cudaGetSymbolAddress((void**)&bar, g_bar);

    cudaFuncSetAttribute(gru_rec, cudaFuncAttributeMaxDynamicSharedMemorySize,
                         REC_SMEM_BYTES);

    const int M = B_ * S_;
    dim3 blk(256);
    dim3 gGI(G3H / 64, M / 128);   // 24 x 512
    dim3 gFC(O_ / 64, M / 128);    //  8 x 512

    // Layer 0: gi0 = x @ W_ih0^T + b_ih0   (rows of x are m = b*S + s)
    sgemm_bias<0><<<gGI, blk>>>(x, Wih0, bih0, gi, M, G3H, I_);

    cudaMemsetAsync(hT, 0, (size_t)2 * H_ * B_ * sizeof(float));
    cudaMemsetAsync(bar, 0, sizeof(unsigned));
    gru_rec<<<GR, RT, REC_SMEM_BYTES>>>(gi, Whh0, bhh0, hT, h0, hid, bar);

    // Layer 1: gi1 = hseq0 @ W_ih1^T + b_ih1  (rows are m = t*B + b)
    sgemm_bias<1><<<gGI, blk>>>(h0, Wih1, bih1, gi, M, G3H, H_);

    cudaMemsetAsync(hT, 0, (size_t)2 * H_ * B_ * sizeof(float));
    cudaMemsetAsync(bar, 0, sizeof(unsigned));
    gru_rec<<<GR, RT, REC_SMEM_BYTES>>>(gi, Whh1, bhh1, hT, h1, hid + B_ * H_, bar);

    // Output FC: logits = hseq1 @ W_fc^T + b_fc, scattered to [B][S][O]
    sgemm_bias<2><<<gFC, blk>>>(h1, Wfc, bfc, out, M, O_, H_);
}

// round 5
// speedup vs baseline: 1.2889x; 1.2889x over previous
#include <cuda_runtime.h>
#include <cstdint>
#include <math.h>

// Problem constants
#define B_   64
#define S_   1024
#define I_   256
#define H_   512
#define O_   512
#define G3H  (3 * H_)

// Recurrence kernel config
#define GR   128   // grid CTAs (<= 148 SMs -> all resident, own barrier is safe)
#define RT   256   // threads per CTA

typedef unsigned long long u64;

// ---------------------------------------------------------------------------
// Scratch (device globals; no runtime allocation allowed)
// ---------------------------------------------------------------------------
__device__ float    g_gi   [(size_t)S_ * G3H * B_];   // gi staging [t][n][b]
__device__ float    g_hseq0[(size_t)S_ * B_ * H_];    // layer-0 outputs [t][b][h]
__device__ float    g_hseq1[(size_t)S_ * B_ * H_];    // layer-1 outputs [t][b][h]
__device__ float    g_hT   [2 * H_ * B_];             // double-buffered transposed h [buf][j][b]
__device__ unsigned g_bar;                             // grid barrier counter

// ---------------------------------------------------------------------------
// f32x2 helpers (Blackwell packed fp32 FMA — 2 MACs per fma-pipe instruction)
// ---------------------------------------------------------------------------
__device__ __forceinline__ u64 pk2(float x) {
    u64 r;
    asm("mov.b64 %0, {%1, %1};" : "=l"(r) : "r"(__float_as_uint(x)));
    return r;
}
__device__ __forceinline__ void fma2(u64& d, u64 a, u64 b) {
    asm("fma.rn.f32x2 %0, %1, %2, %0;" : "+l"(d) : "l"(a), "l"(b));
}
__device__ __forceinline__ float2 up2(u64 u) {
    unsigned lo, hi;
    asm("mov.b64 {%0, %1}, %2;" : "=r"(lo), "=r"(hi) : "l"(u));
    return make_float2(__uint_as_float(lo), __uint_as_float(hi));
}
__device__ __forceinline__ void cpa16(float* smem, const float* g) {
    unsigned s = (unsigned)__cvta_generic_to_shared(smem);
    asm volatile("cp.async.cg.shared.global [%0], [%1], 16;" :: "r"(s), "l"(g));
}

// ---------------------------------------------------------------------------
// SGEMM with bias:  C[M,N] = A[M,K] @ Bw[N,K]^T + bias[N]
// BM=128, BN=64, BK=16, 256 threads, 8x4 per thread via f32x2 (4 m-pairs x 4 n).
// MODE epilogue scatter:
//   0: A rows m = b*S + s   -> out[t][n][b]
//   1: A rows m = t*B + b   -> out[t][n][b]
//   2: A rows m = t*B + b   -> out[b][t][n]
// ---------------------------------------------------------------------------
template <int MODE>
__global__ void __launch_bounds__(256)
sgemm_bias(const float* __restrict__ A, const float* __restrict__ Bw,
           const float* __restrict__ bias, float* __restrict__ out,
           int M, int N, int K)
{
    __shared__ float As[16][132];   // row stride 528 B (16B multiple)
    __shared__ float Bs[16][68];    // row stride 272 B (16B multiple)

    const int tid = threadIdx.x;
    const int m0  = blockIdx.y * 128;
    const int n0  = blockIdx.x * 64;
    const int tx  = tid & 15;       // 4 cols of N
    const int ty  = tid >> 4;       // 8 rows of M (4 pairs)

    const float* Ab = A  + (size_t)m0 * K;
    const float* Bb = Bw + (size_t)n0 * K;

    u64 acc[4][4];
#pragma unroll
    for (int i = 0; i < 4; i++)
#pragma unroll
        for (int j = 0; j < 4; j++) acc[i][j] = 0ull;

    const int lr = tid >> 2;
    const int lk = (tid & 3) * 4;

    for (int kt = 0; kt < K; kt += 16) {
#pragma unroll
        for (int p = 0; p < 2; p++) {
            float4 v = *(const float4*)&Ab[(size_t)(lr + p * 64) * K + kt + lk];
            As[lk + 0][lr + p * 64] = v.x;
            As[lk + 1][lr + p * 64] = v.y;
            As[lk + 2][lr + p * 64] = v.z;
            As[lk + 3][lr + p * 64] = v.w;
        }
        {
            float4 v = *(const float4*)&Bb[(size_t)lr * K + kt + lk];
            Bs[lk + 0][lr] = v.x;
            Bs[lk + 1][lr] = v.y;
            Bs[lk + 2][lr] = v.z;
            Bs[lk + 3][lr] = v.w;
        }
        __syncthreads();

#pragma unroll
        for (int k = 0; k < 16; k++) {
            float4 bv = *(const float4*)&Bs[k][tx * 4];
            u64 bp0 = pk2(bv.x), bp1 = pk2(bv.y), bp2 = pk2(bv.z), bp3 = pk2(bv.w);
            ulonglong2 a01 = *(const ulonglong2*)&As[k][ty * 8];
            ulonglong2 a23 = *(const ulonglong2*)&As[k][ty * 8 + 4];
            u64 ap[4] = {a01.x, a01.y, a23.x, a23.y};
#pragma unroll
            for (int i = 0; i < 4; i++) {
                fma2(acc[i][0], ap[i], bp0);
                fma2(acc[i][1], ap[i], bp1);
                fma2(acc[i][2], ap[i], bp2);
                fma2(acc[i][3], ap[i], bp3);
            }
        }
        __syncthreads();
    }

    // unpack to scalar
    float accf[8][4];
#pragma unroll
    for (int i = 0; i < 4; i++)
#pragma unroll
        for (int j = 0; j < 4; j++) {
            float2 v = up2(acc[i][j]);
            accf[2 * i + 0][j] = v.x;
            accf[2 * i + 1][j] = v.y;
        }

    float bv[4];
    *(float4*)bv = *(const float4*)&bias[n0 + tx * 4];

#pragma unroll
    for (int i = 0; i < 8; i++) {
        int m = m0 + ty * 8 + i;
        if (MODE == 2) {
            int t = m >> 6, b = m & 63;
            float4 c;
            c.x = accf[i][0] + bv[0];
            c.y = accf[i][1] + bv[1];
            c.z = accf[i][2] + bv[2];
            c.w = accf[i][3] + bv[3];
            *(float4*)&out[((size_t)b * S_ + t) * O_ + n0 + tx * 4] = c;
        } else {
            int t, b;
            if (MODE == 0) { t = m & (S_ - 1); b = m >> 10; }
            else           { t = m >> 6;       b = m & 63;  }
#pragma unroll
            for (int j = 0; j < 4; j++) {
                int n = n0 + tx * 4 + j;
                out[((size_t)t * G3H + n) * B_ + b] = accf[i][j] + bv[j];
            }
        }
    }
}

// ---------------------------------------------------------------------------
// Persistent GRU recurrence (one layer). CTA c owns H-columns [4c, 4c+4).
// Per step: each warp owns a 64-k split; it streams its own 16 KB h-chunk via
// cp.async in 4 commit-groups and computes f32x2 partial dot products as the
// sub-chunks land. Partials reduced via smem, gates applied, h exchanged via
// global hT, grid-synced with an atomic counter (all CTAs wave-1 resident).
// smem (floats): hs[512][64] @0 (128K) | Ws[512][4][4] @32768 (32K) |
//                P[8][4][64][3] @40960 (24K) | gis[3][4][64] @47104 | bh @47872
// ---------------------------------------------------------------------------
#define REC_SMEM_FLOATS 47884
#define REC_SMEM_BYTES  (REC_SMEM_FLOATS * 4)

__device__ __forceinline__ float sigmoidf_(float x) {
    return 1.f / (1.f + expf(-x));
}

template <int SC>
__device__ __forceinline__ void rec_chunk(const float* __restrict__ hs,
                                          const float4* __restrict__ Ws4,
                                          int k0, int jc, int hbase,
                                          u64* c0, u64* c1, u64* c2)
{
    asm volatile("cp.async.wait_group %0;" :: "n"(3 - SC));
    __syncwarp();
    const ulonglong2* hs2 = (const ulonglong2*)hs;
    const int kb = k0 + SC * 16;
#pragma unroll 4
    for (int k = kb; k < kb + 16; k++) {
        float4 w = Ws4[k * 4 + jc];
        u64 wx = pk2(w.x), wy = pk2(w.y), wz = pk2(w.z);
        ulonglong2 hA = hs2[k * 16 + hbase];
        ulonglong2 hB = hs2[k * 16 + hbase + 1];
        fma2(c0[0], hA.x, wx); fma2(c1[0], hA.x, wy); fma2(c2[0], hA.x, wz);
        fma2(c0[1], hA.y, wx); fma2(c1[1], hA.y, wy); fma2(c2[1], hA.y, wz);
        fma2(c0[2], hB.x, wx); fma2(c1[2], hB.x, wy); fma2(c2[2], hB.x, wz);
        fma2(c0[3], hB.y, wx); fma2(c1[3], hB.y, wy); fma2(c2[3], hB.y, wz);
    }
}

__global__ void __launch_bounds__(RT, 1)
gru_rec(const float* __restrict__ gi,    // [S][3H][B]
        const float* __restrict__ Whh,   // [3H][H]
        const float* __restrict__ bhh,   // [3H]
        float* __restrict__ hT,          // [2][H][B]
        float* __restrict__ hseq,        // [S][B][H]
        float* __restrict__ hfin,        // [B][H]
        unsigned* __restrict__ bar)
{
    extern __shared__ float sm[];
    float* hs  = sm;              // 32768 floats
    float* Ws  = sm + 32768;      // 8192
    float* P   = sm + 40960;      // 6144
    float* gis = sm + 47104;      // 768
    float* bh  = sm + 47872;      // 12

    const int tid   = threadIdx.x;
    const int jbase = blockIdx.x * 4;

    // Preload W_hh slice (12 rows x 512), k-major, gates packed in float4 slots.
    for (int i = tid; i < 12 * 512; i += RT) {
        int k = i & 511;
        int r = i >> 9;
        int g = r % 3, jc = r / 3;
        Ws[(k * 4 + jc) * 4 + g] = Whh[((size_t)(g * H_ + jbase + jc)) * H_ + k];
    }
    if (tid < 12) {
        int g = tid % 3, jc = tid / 3;
        bh[jc * 3 + g] = bhh[g * H_ + jbase + jc];
    }
    __syncthreads();

    // Compute mapping: warp = k-split (64 k), lane -> (jc, 8 b's = 4 pairs)
    const int ws    = tid >> 5;
    const int lane  = tid & 31;
    const int jc    = lane >> 3;
    const int b0    = (lane & 7) * 8;
    const int hbase = b0 >> 2;
    const int k0    = ws * 64;
    const float4* Ws4 = (const float4*)Ws;

    // Finalize mapping: one (b, jc) per thread
    const int fb  = tid & 63;
    const int fjc = tid >> 6;
    const int fj  = jbase + fjc;

    for (int t = 0; t < S_; t++) {
        const float* hsrc = hT + (t & 1) * (H_ * B_);

        // Stream own 16KB h-chunk as 4 cp.async groups (4KB each)
#pragma unroll
        for (int sc = 0; sc < 4; sc++) {
            const float* s0 = hsrc + (k0 + sc * 16) * 64;
            float*       d0 = hs   + (k0 + sc * 16) * 64;
#pragma unroll
            for (int i = 0; i < 8; i++)
                cpa16(d0 + (lane + i * 32) * 4, s0 + (lane + i * 32) * 4);
            asm volatile("cp.async.commit_group;");
        }

        // Stage this step's gi slice (independent of h; overlaps cp.async)
#pragma unroll
        for (int r = 0; r < 3; r++) {
            int i = tid + r * RT;
            int b = i & 63, row = i >> 6;
            int g = row % 3, jcc = row / 3;
            gis[(g * 4 + jcc) * 64 + b] =
                gi[((size_t)t * G3H + g * H_ + jbase + jcc) * B_ + b];
        }

        // Partial dot products, pipelined against the streaming loads
        u64 c0[4] = {0, 0, 0, 0}, c1[4] = {0, 0, 0, 0}, c2[4] = {0, 0, 0, 0};
        rec_chunk<0>(hs, Ws4, k0, jc, hbase, c0, c1, c2);
        rec_chunk<1>(hs, Ws4, k0, jc, hbase, c0, c1, c2);
        rec_chunk<2>(hs, Ws4, k0, jc, hbase, c0, c1, c2);
        rec_chunk<3>(hs, Ws4, k0, jc, hbase, c0, c1, c2);

        // Store partials (24 floats -> 6 float4)
        {
            __align__(16) float val[24];
#pragma unroll
            for (int p = 0; p < 4; p++) {
                float2 f0 = up2(c0[p]), f1 = up2(c1[p]), f2 = up2(c2[p]);
                val[(2 * p) * 3 + 0] = f0.x;  val[(2 * p + 1) * 3 + 0] = f0.y;
                val[(2 * p) * 3 + 1] = f1.x;  val[(2 * p + 1) * 3 + 1] = f1.y;
                val[(2 * p) * 3 + 2] = f2.x;  val[(2 * p + 1) * 3 + 2] = f2.y;
            }
            float* pb = P + ((ws * 4 + jc) * 64 + b0) * 3;
#pragma unroll
            for (int q = 0; q < 6; q++) ((float4*)pb)[q] = ((const float4*)val)[q];
        }
        __syncthreads();

        // Reduce k-splits + gate math + h update (one (b,jc) per thread)
        {
            float gh0 = 0.f, gh1 = 0.f, gh2 = 0.f;
#pragma unroll
            for (int s = 0; s < 8; s++) {
                const float* pp = P + ((s * 4 + fjc) * 64 + fb) * 3;
                gh0 += pp[0];
                gh1 += pp[1];
                gh2 += pp[2];
            }
            gh0 += bh[fjc * 3 + 0];
            gh1 += bh[fjc * 3 + 1];
            gh2 += bh[fjc * 3 + 2];

            float gir = gis[(0 * 4 + fjc) * 64 + fb];
            float giz = gis[(1 * 4 + fjc) * 64 + fb];
            float gin = gis[(2 * 4 + fjc) * 64 + fb];

            float r_ = sigmoidf_(gir + gh0);
            float z_ = sigmoidf_(giz + gh1);
            float n_ = tanhf(gin + r_ * gh2);
            float hold = hs[fj * 64 + fb];
            float hn = (1.f - z_) * n_ + z_ * hold;

            hT[((t & 1) ^ 1) * H_ * B_ + fj * 64 + fb] = hn;
            hseq[(size_t)t * B_ * H_ + (size_t)fb * H_ + fj] = hn;
            if (t == S_ - 1) hfin[fb * H_ + fj] = hn;
        }
        __syncthreads();

        // Grid barrier (monotonic counter; all CTAs resident -> no deadlock)
        if (tid == 0) {
            __threadfence();
            atomicAdd(bar, 1u);
            const unsigned tgt = (unsigned)(t + 1) * GR;
            while (*((volatile unsigned*)bar) < tgt) { }
            __threadfence();
        }
        __syncthreads();
    }
}

// ---------------------------------------------------------------------------
// Launch
// ---------------------------------------------------------------------------
extern "C" void kernel_launch(void* const* d_in, const int* in_sizes, int n_in,
                              void* d_out, int out_size)
{
    const float* x    = (const float*)d_in[0];
    const float* Wih0 = (const float*)d_in[1];
    const float* Whh0 = (const float*)d_in[2];
    const float* bih0 = (const float*)d_in[3];
    const float* bhh0 = (const float*)d_in[4];
    const float* Wih1 = (const float*)d_in[5];
    const float* Whh1 = (const float*)d_in[6];
    const float* bih1 = (const float*)d_in[7];
    const float* bhh1 = (const float*)d_in[8];
    const float* Wfc  = (const float*)d_in[9];
    const float* bfc  = (const float*)d_in[10];

    float* out = (float*)d_out;                       // logits [B][S][O]
    float* hid = out + (size_t)B_ * S_ * O_;          // hidden [2][B][H]

    float *gi, *h0, *h1, *hT;
    unsigned* bar;
    cudaGetSymbolAddress((void**)&gi,  g_gi);
    cudaGetSymbolAddress((void**)&h0,  g_hseq0);
    cudaGetSymbolAddress((void**)&h1,  g_hseq1);
    cudaGetSymbolAddress((void**)&hT,  g_hT);
    cudaGetSymbolAddress((void**)&bar, g_bar);

    cudaFuncSetAttribute(gru_rec, cudaFuncAttributeMaxDynamicSharedMemorySize,
                         REC_SMEM_BYTES);

    const int M = B_ * S_;
    dim3 blk(256);
    dim3 gGI(G3H / 64, M / 128);   // 24 x 512
    dim3 gFC(O_ / 64, M / 128);    //  8 x 512

    // Layer 0: gi0 = x @ W_ih0^T + b_ih0
    sgemm_bias<0><<<gGI, blk>>>(x, Wih0, bih0, gi, M, G3H, I_);

    cudaMemsetAsync(hT, 0, (size_t)2 * H_ * B_ * sizeof(float));
    cudaMemsetAsync(bar, 0, sizeof(unsigned));
    gru_rec<<<GR, RT, REC_SMEM_BYTES>>>(gi, Whh0, bhh0, hT, h0, hid, bar);

    // Layer 1: gi1 = hseq0 @ W_ih1^T + b_ih1
    sgemm_bias<1><<<gGI, blk>>>(h0, Wih1, bih1, gi, M, G3H, H_);

    cudaMemsetAsync(hT, 0, (size_t)2 * H_ * B_ * sizeof(float));
    cudaMemsetAsync(bar, 0, sizeof(unsigned));
    gru_rec<<<GR, RT, REC_SMEM_BYTES>>>(gi, Whh1, bhh1, hT, h1, hid + B_ * H_, bar);

    // Output FC: logits = hseq1 @ W_fc^T + b_fc
    sgemm_bias<2><<<gFC, blk>>>(h1, Wfc, bfc, out, M, O_, H_);
}